// round 12
// baseline (speedup 1.0000x reference)
#include <cuda_runtime.h>
#include <math.h>
#include <stdint.h>
#include <stddef.h>

// DBN beat decoder: 4-CTA cluster per batch, j-partitioned chunked Viterbi.
// tau = 28..109 (82 tempi), S = 5617, B = 4, T = 6000.
#define NI     82
#define TROW   84       // trans_t row stride (i-major)
#define LR     85       // Lbuf row stride
#define LBSZ   (CHUNK * LR)
#define S_TOT  5617
#define S_PAD  5632
#define T_LEN  6000
#define BATCH  4
#define TPB    1024
#define CHUNK  28
#define NFULL  214      // full chunks cover t = 1..5992
#define CLN    4
#define PBMAX  8064     // max partial buf floats (12 x 28 x 24)
#define CIDXM  1312     // max cidx entries (164 x 8)

__device__ float g_L[(size_t)BATCH * T_LEN * NI];   // exact L for lazy backtrace

__device__ __forceinline__ int first_of(int j) { return 28 * j + (j * (j - 1)) / 2; }
__device__ __forceinline__ int last_of(int j)  { return first_of(j) + 27 + j; }

__device__ __forceinline__ uint32_t smem_u32(const void* p) {
    uint32_t a;
    asm("{ .reg .u64 t; cvta.to.shared.u64 t, %1; cvt.u32.u64 %0, t; }" : "=r"(a) : "l"(p));
    return a;
}
__device__ __forceinline__ uint32_t mapa_rank(uint32_t addr, uint32_t rank) {
    uint32_t r;
    asm("mapa.shared::cluster.u32 %0, %1, %2;" : "=r"(r) : "r"(addr), "r"(rank));
    return r;
}
__device__ __forceinline__ void st_cluster(uint32_t addr, float v) {
    asm volatile("st.shared::cluster.f32 [%0], %1;" :: "r"(addr), "f"(v) : "memory");
}
#define CL_ARRIVE() asm volatile("barrier.cluster.arrive.aligned;" ::: "memory")
#define CL_WAIT()   asm volatile("barrier.cluster.wait.aligned;"   ::: "memory")

__global__ __launch_bounds__(TPB, 1)
void dbn_kernel(const float* __restrict__ logit, float* __restrict__ out)
{
    extern __shared__ char smraw[];
    float* trans_t = (float*)smraw;                 // [84][84] trans_t[i][j]
    float* dbuf    = trans_t + TROW * TROW;         // [2][5632] delta (own partition live)
    float* Lbuf    = dbuf + 2 * S_PAD;              // [2][28][85]
    float* Pbuf    = Lbuf + 2 * LBSZ;               // partial maxes [NSP][28][PW]
    float* blp     = Pbuf + PBMAX;                  // 6000
    float* nlp     = blp + T_LEN;                   // 6000
    float* redv    = nlp + T_LEN;                   // 32
    int*   redi    = (int*)(redv + 32);             // 32
    int*   cidx    = redi + 32;                     // 1312
    unsigned char* isf = (unsigned char*)(cidx + CIDXM);  // 5632

    const int tid = threadIdx.x;
    const int b   = blockIdx.x / CLN;
    uint32_t rnk;
    asm("mov.u32 %0, %%cluster_ctarank;" : "=r"(rnk));
    const int r = (int)rnk;

    const float* lg = logit + (size_t)b * T_LEN;
    float* Lg   = g_L + (size_t)b * T_LEN * NI;
    float* outb = out + (size_t)b * T_LEN;

    // per-rank partition constants
    const int JBv[4]  = {0, 24, 44, 64};
    const int NJv[4]  = {24, 20, 20, 18};
    const int NQv[4]  = {6, 5, 5, 5};
    const int NSPv[4] = {12, 14, 14, 14};
    const int ISPv[4] = {7, 6, 6, 6};
    const int NMv[4]  = {276, 670, 1070, 1305};
    const int NMb[4]  = {0, 276, 946, 2016};
    const int SLOv[4] = {0, 948, 2178, 3808};
    const int SHIv[4] = {948, 2178, 3808, 5617};

    const int JB  = JBv[r];
    const int NJ  = NJv[r];
    const int NQ  = NQv[r];
    const int NSP = NSPv[r];
    const int ISP = ISPv[r];
    const int NM  = NMv[r];
    const int NA  = NJ * CHUNK;
    const int ATH = NA / 2;
    const int PW  = 4 * NQ;
    const int QSZ = CHUNK * PW;
    const int BTH = NQ * 14 * NSP;
    const int NC  = (NM + 7) / 8;

    // DSMEM peer bases (3 peers)
    uint32_t peerL[3], peerD[3];
    {
        uint32_t lb = smem_u32(Lbuf), db = smem_u32(dbuf);
#pragma unroll
        for (int m = 0; m < 3; ++m) {
            uint32_t pr = (rnk + 1u + (uint32_t)m) & 3u;
            peerL[m] = mapa_rank(lb, pr);
            peerD[m] = mapa_rank(db, pr);
        }
    }

    // ================= setup =================
    if (tid < NI) {               // trans row i = tid (fp64, matches numpy)
        double ti = (double)(28 + tid);
        double sum = 0.0;
        for (int jj = 0; jj < NI; ++jj)
            sum += exp(-100.0 * fabs((double)(28 + jj) / ti - 1.0));
        double ls = log(sum);
        for (int jj = 0; jj < NI; ++jj) {
            double rr = -100.0 * fabs((double)(28 + jj) / ti - 1.0);
            trans_t[tid * TROW + jj] = (float)(rr - ls);
        }
        trans_t[tid * TROW + 82] = -1e30f;
        trans_t[tid * TROW + 83] = -1e30f;
    }
    for (int s = tid; s < S_PAD; s += TPB) isf[s] = 0;
    for (int t = tid; t < T_LEN; t += TPB) {
        float x  = lg[t];
        float l1 = log1pf(expf(-fabsf(x)));
        blp[t] = fminf(x, 0.0f) - l1;
        nlp[t] = fminf(-x, 0.0f) - l1;
    }
    // cidx: own main-state ids (p >= 28), global triangular index offset by rank
    for (int k = tid; k < 8 * NC; k += TPB) {
        if (k < NM) {
            int kk = k + NMb[r];
            int j = (int)((1.0 + sqrt(8.0 * (double)kk + 1.0)) * 0.5);
            while ((j * (j + 1)) / 2 <= kk) ++j;
            while ((j * (j - 1)) / 2 > kk)  --j;
            int m = kk - (j * (j - 1)) / 2;
            cidx[k] = first_of(j) + 28 + m;
        } else cidx[k] = S_PAD - 1;
    }
    __syncthreads();
    if (tid < NI) isf[first_of(tid)] = 1;
    __syncthreads();

    const float logS = logf((float)S_TOT);
    for (int s = tid; s < S_TOT; s += TPB)
        dbuf[s] = (isf[s] ? blp[0] : nlp[0]) - logS;

    // ---- per-thread chunk-invariant constants ----
    // A tasks (2/thread): task = g*NJ + q, j = JB + q
    int Ag[2], Aoff[2], Alb[2], Agn[2];
#pragma unroll
    for (int m = 0; m < 2; ++m) {
        int task = 2 * tid + m;
        if (task < NA) {
            int g = task / NJ, q = task - g * NJ, j = JB + q;
            Ag[m] = g; Aoff[m] = last_of(j) - g;
            Alb[m] = g * LR + j; Agn[m] = g * NI + j;
        } else { Ag[m] = 0; Aoff[m] = 0; Alb[m] = 0; Agn[m] = 0; }
    }
    // C-top tasks (2/thread): task = p*NJ + q
    int Cth[2], Cpb[2], Cdn[2], Cbf[2];
#pragma unroll
    for (int m = 0; m < 2; ++m) {
        int task = 2 * tid + m;
        if (task < NA) {
            int p = task / NJ, q = task - p * NJ, j = JB + q;
            Cth[m] = 28 - p; Cpb[m] = (27 - p) * PW + q;
            Cdn[m] = first_of(j) + p; Cbf[m] = 27 - p;
        } else { Cth[m] = 28; Cpb[m] = 0; Cdn[m] = 0; Cbf[m] = 0; }
    }
    // B mapping (tid < BTH): i-slice h, local j-quad jq, frame pair f0
    const int h    = tid / (NQ * 14);
    const int brem = tid - h * (NQ * 14);
    const int jq   = brem / 14;
    const int f0   = 2 * (brem - 14 * jq);
    const int Bi0  = h * ISP;
    const int Bi1  = (Bi0 + ISP < NI) ? (Bi0 + ISP) : NI;
    __syncthreads();

    // ================= 214 full chunks =================
    for (int c = 0; c < NFULL; ++c) {
        const int t0 = 1 + CHUNK * c;
        const float* dprev = dbuf + (c & 1) * S_PAD;
        float*       dnew  = dbuf + ((c + 1) & 1) * S_PAD;
        const float* np    = nlp + t0;
        const int    lsel  = (c & 1) * LBSZ;
        float*       Lw    = Lbuf + lsel;
        float* Lgc = Lg + (size_t)t0 * NI;

        // ---- A: own L chains (2-way ILP), write local + 3 peers + global ----
        if (tid < ATH) {
            float a0 = dprev[Aoff[0]];
            float a1 = dprev[Aoff[1]];
            int kmax = Ag[0] > Ag[1] ? Ag[0] : Ag[1];
#pragma unroll 4
            for (int k = 0; k < kmax; ++k) {
                float v = np[k];
                if (k < Ag[0]) a0 += v;
                if (k < Ag[1]) a1 += v;
            }
            uint32_t o0 = (uint32_t)(lsel + Alb[0]) * 4u;
            uint32_t o1 = (uint32_t)(lsel + Alb[1]) * 4u;
            Lw[Alb[0]] = a0; Lw[Alb[1]] = a1;
            st_cluster(peerL[0] + o0, a0); st_cluster(peerL[0] + o1, a1);
            st_cluster(peerL[1] + o0, a0); st_cluster(peerL[1] + o1, a1);
            st_cluster(peerL[2] + o0, a0); st_cluster(peerL[2] + o1, a1);
            Lgc[Agn[0]] = a0; Lgc[Agn[1]] = a1;
        }
        CL_ARRIVE();

        // ---- C-main in the arrive->wait gap (purely local) ----
        if (tid >= ATH && tid < ATH + NC) {
            const int base = 8 * (tid - ATH);
            int s0 = cidx[base],     s1 = cidx[base + 1];
            int s2 = cidx[base + 2], s3 = cidx[base + 3];
            int s4 = cidx[base + 4], s5 = cidx[base + 5];
            int s6 = cidx[base + 6], s7 = cidx[base + 7];
            float m0 = dprev[s0 - CHUNK], m1 = dprev[s1 - CHUNK];
            float m2 = dprev[s2 - CHUNK], m3 = dprev[s3 - CHUNK];
            float m4 = dprev[s4 - CHUNK], m5 = dprev[s5 - CHUNK];
            float m6 = dprev[s6 - CHUNK], m7 = dprev[s7 - CHUNK];
#pragma unroll
            for (int k = 0; k < CHUNK; ++k) {
                float v = np[k];
                m0 += v; m1 += v; m2 += v; m3 += v;
                m4 += v; m5 += v; m6 += v; m7 += v;
            }
            if (base     < NM) dnew[s0] = m0;
            if (base + 1 < NM) dnew[s1] = m1;
            if (base + 2 < NM) dnew[s2] = m2;
            if (base + 3 < NM) dnew[s3] = m3;
            if (base + 4 < NM) dnew[s4] = m4;
            if (base + 5 < NM) dnew[s5] = m5;
            if (base + 6 < NM) dnew[s6] = m6;
            if (base + 7 < NM) dnew[s7] = m7;
        }
        CL_WAIT();   // all CTAs' L complete everywhere

        // ---- B: own j, i-slice, nearly all threads ----
        if (tid < BTH) {
            const float4* tc = (const float4*)trans_t + ((JB >> 2) + jq);
            const float*  L0 = Lbuf + lsel + f0 * LR;
            const float*  L1 = L0 + LR;
            float4 A0 = make_float4(-1e30f, -1e30f, -1e30f, -1e30f);
            float4 A1 = A0;
#pragma unroll 4
            for (int i = Bi0; i < Bi1; ++i) {
                float4 tv = tc[i * (TROW / 4)];
                float l0 = L0[i];
                float l1 = L1[i];
                A0.x = fmaxf(A0.x, l0 + tv.x); A0.y = fmaxf(A0.y, l0 + tv.y);
                A0.z = fmaxf(A0.z, l0 + tv.z); A0.w = fmaxf(A0.w, l0 + tv.w);
                A1.x = fmaxf(A1.x, l1 + tv.x); A1.y = fmaxf(A1.y, l1 + tv.y);
                A1.z = fmaxf(A1.z, l1 + tv.z); A1.w = fmaxf(A1.w, l1 + tv.w);
            }
            float* Ph = Pbuf + h * QSZ;
            *(float4*)(Ph + f0 * PW + 4 * jq)       = A0;
            *(float4*)(Ph + (f0 + 1) * PW + 4 * jq) = A1;
        }
        __syncthreads();

        // ---- C-top: combine NSP partials, + blp, chain (2-way ILP) ----
        if (tid < ATH) {
            float c0 = -1e30f, c1 = -1e30f;
            for (int hh = 0; hh < NSP; ++hh) {
                const float* Ph = Pbuf + hh * QSZ;
                c0 = fmaxf(c0, Ph[Cpb[0]]);
                c1 = fmaxf(c1, Ph[Cpb[1]]);
            }
            c0 += blp[t0 + Cbf[0]];
            c1 += blp[t0 + Cbf[1]];
            int kmin = Cth[0] < Cth[1] ? Cth[0] : Cth[1];
#pragma unroll 4
            for (int k = kmin; k < CHUNK; ++k) {
                float v = np[k];
                if (k >= Cth[0]) c0 += v;
                if (k >= Cth[1]) c1 += v;
            }
            dnew[Cdn[0]] = c0;
            dnew[Cdn[1]] = c1;
        }
        __syncthreads();
    }

    // ================= broadcast final delta partitions =================
    int ping = NFULL & 1;   // buffer holding delta at t=5992
    {
        const int slo = SLOv[r], shi = SHIv[r];
        const float* dp = dbuf + ping * S_PAD;
        const uint32_t off = (uint32_t)(ping * S_PAD) * 4u;
        for (int s = slo + tid; s < shi; s += TPB) {
            float v = dp[s];
            st_cluster(peerD[0] + off + 4u * s, v);
            st_cluster(peerD[1] + off + 4u * s, v);
            st_cluster(peerD[2] + off + 4u * s, v);
        }
    }
    CL_ARRIVE(); CL_WAIT();

    // ================= tail t = 5993..5999 (redundant, all CTAs) =========
    for (int t = 1 + CHUNK * NFULL; t < T_LEN; ++t) {
        const float* dprev = dbuf + ping * S_PAD;
        float*       dnew  = dbuf + (ping ^ 1) * S_PAD;
        if (tid < NI) {
            float lv = dprev[last_of(tid)];
            Pbuf[tid] = lv;                   // scratch
            Lg[(size_t)t * NI + tid] = lv;
        }
        __syncthreads();
        if (tid < NI) {
            float m = -1e30f;
            for (int i = 0; i < NI; ++i)
                m = fmaxf(m, Pbuf[i] + trans_t[i * TROW + tid]);
            dnew[first_of(tid)] = m + blp[t];
        } else if (tid >= 128) {
            float nb = nlp[t];
            for (int s = tid - 128; s < S_TOT; s += TPB - 128)
                if (!isf[s]) dnew[s] = dprev[s - 1] + nb;
        }
        __syncthreads();
        ping ^= 1;
    }

    // ================= final argmax (first-max = smallest s) ==============
    const float* df = dbuf + ping * S_PAD;
    if (r == 0) for (int t = tid; t < T_LEN; t += TPB) outb[t] = 0.0f;

    float bv = -INFINITY; int bs = 0x7fffffff;
    for (int s = tid; s < S_TOT; s += TPB) {
        float v = df[s];
        if (v > bv) { bv = v; bs = s; }
    }
#pragma unroll
    for (int off = 16; off; off >>= 1) {
        float ov = __shfl_xor_sync(0xffffffffu, bv, off);
        int   oi = __shfl_xor_sync(0xffffffffu, bs, off);
        if (ov > bv || (ov == bv && oi < bs)) { bv = ov; bs = oi; }
    }
    if ((tid & 31) == 0) { redv[tid >> 5] = bv; redi[tid >> 5] = bs; }
    __syncthreads();

    // ================= backtrace (rank 0, warp 0) =========================
    if (r == 0 && tid < 32) {
        bv = redv[tid]; bs = redi[tid];
#pragma unroll
        for (int off = 16; off; off >>= 1) {
            float ov = __shfl_xor_sync(0xffffffffu, bv, off);
            int   oi = __shfl_xor_sync(0xffffffffu, bs, off);
            if (ov > bv || (ov == bv && oi < bs)) { bv = ov; bs = oi; }
        }
        int lo = 0, hi = 81;
        while (lo < hi) { int mid = (lo + hi + 1) >> 1; if (first_of(mid) <= bs) lo = mid; else hi = mid - 1; }
        int j   = lo;
        int pos = bs - first_of(j);
        int t   = T_LEN - 1;
        const int lane = tid;

        while (true) {
            int te = t - pos;
            if (te < 0) break;
            if (lane == 0) {
                float x  = lg[te];
                float sg = 1.0f / (1.0f + expf(-x));
                if (sg >= 0.05f) outb[te] = 1.0f;
            }
            if (te == 0) break;
            const float* Lr = Lg + (size_t)te * NI;
            float best = -INFINITY; int bi = 0x7fffffff;
            for (int i = lane; i < NI; i += 32) {
                float cc = Lr[i] + trans_t[i * TROW + j];
                if (cc > best) { best = cc; bi = i; }
            }
#pragma unroll
            for (int off = 16; off; off >>= 1) {
                float ov = __shfl_xor_sync(0xffffffffu, best, off);
                int   oi = __shfl_xor_sync(0xffffffffu, bi,   off);
                if (ov > best || (ov == best && oi < bi)) { best = ov; bi = oi; }
            }
            j   = bi;
            pos = 27 + j;
            t   = te - 1;
        }
    }
    CL_ARRIVE(); CL_WAIT();
}

extern "C" void kernel_launch(void* const* d_in, const int* in_sizes, int n_in,
                              void* d_out, int out_size)
{
    (void)in_sizes; (void)n_in; (void)out_size;
    const float* logit = (const float*)d_in[0];
    float* out = (float*)d_out;

    const size_t smem = (size_t)(TROW * TROW + 2 * S_PAD + 2 * LBSZ + PBMAX
                                 + 2 * T_LEN + 64 + CIDXM) * 4 + S_PAD;
    cudaFuncSetAttribute(dbn_kernel,
                         cudaFuncAttributeMaxDynamicSharedMemorySize, (int)smem);

    cudaLaunchConfig_t cfg = {};
    cfg.gridDim  = dim3(CLN * BATCH, 1, 1);
    cfg.blockDim = dim3(TPB, 1, 1);
    cfg.dynamicSmemBytes = smem;
    cfg.stream = 0;
    cudaLaunchAttribute attrs[1];
    attrs[0].id = cudaLaunchAttributeClusterDimension;
    attrs[0].val.clusterDim.x = CLN;
    attrs[0].val.clusterDim.y = 1;
    attrs[0].val.clusterDim.z = 1;
    cfg.attrs = attrs;
    cfg.numAttrs = 1;
    cudaLaunchKernelEx(&cfg, dbn_kernel, logit, out);
}

// round 14
// speedup vs baseline: 1.5098x; 1.5098x over previous
#include <cuda_runtime.h>
#include <math.h>
#include <stdint.h>
#include <stddef.h>

// DBN beat decoder: 2-CTA cluster per batch, j-partitioned chunked Viterbi,
// cluster-barrier latency hidden behind local C-main.
// tau = 28..109 (82 tempi), S = 5617, B = 4, T = 6000.
#define NI     82
#define TROW   84       // trans_t row stride (i-major)
#define LR     85       // Lbuf row stride
#define LBSZ   (CHUNK * LR)
#define S_TOT  5617
#define S_PAD  5632
#define T_LEN  6000
#define BATCH  4
#define TPB    1024
#define CHUNK  28
#define NFULL  214      // full chunks cover t = 1..5992
#define SPLITJ 44
#define SPLITS 2178     // first_of(44)
#define NM0    946      // main states (p>=28) in j<44
#define NM1    2375     // main states in j>=44
#define CIDXN  2384
#define PBMAX  7840     // max partial floats: CTA1 7 x 28 x 40

__device__ float g_L[(size_t)BATCH * T_LEN * NI];   // exact L for lazy backtrace

__device__ __forceinline__ int first_of(int j) { return 28 * j + (j * (j - 1)) / 2; }
__device__ __forceinline__ int last_of(int j)  { return first_of(j) + 27 + j; }

__device__ __forceinline__ uint32_t smem_u32(const void* p) {
    uint32_t a;
    asm("{ .reg .u64 t; cvta.to.shared.u64 t, %1; cvt.u32.u64 %0, t; }" : "=r"(a) : "l"(p));
    return a;
}
__device__ __forceinline__ uint32_t mapa_rank(uint32_t addr, uint32_t rank) {
    uint32_t r;
    asm("mapa.shared::cluster.u32 %0, %1, %2;" : "=r"(r) : "r"(addr), "r"(rank));
    return r;
}
__device__ __forceinline__ void st_cluster(uint32_t addr, float v) {
    asm volatile("st.shared::cluster.f32 [%0], %1;" :: "r"(addr), "f"(v) : "memory");
}
#define CL_ARRIVE() asm volatile("barrier.cluster.arrive.aligned;" ::: "memory")
#define CL_WAIT()   asm volatile("barrier.cluster.wait.aligned;"   ::: "memory")

__global__ __launch_bounds__(TPB, 1)
void dbn_kernel(const float* __restrict__ logit, float* __restrict__ out)
{
    extern __shared__ char smraw[];
    float* trans_t = (float*)smraw;                 // [84][84] trans_t[i][j]
    float* dbuf    = trans_t + TROW * TROW;         // [2][5632] delta (own partition live)
    float* Lbuf    = dbuf + 2 * S_PAD;              // [2][28][85]
    float* Pbuf    = Lbuf + 2 * LBSZ;               // B partials [NSP][28][PW]
    float* blp     = Pbuf + PBMAX;                  // 6000
    float* nlp     = blp + T_LEN;                   // 6000
    float* redv    = nlp + T_LEN;                   // 32
    int*   redi    = (int*)(redv + 32);             // 32
    int*   cidx    = redi + 32;                     // 2384
    unsigned char* isf = (unsigned char*)(cidx + CIDXN);  // 5632

    const int tid = threadIdx.x;
    const int b   = blockIdx.x >> 1;
    uint32_t rnk;
    asm("mov.u32 %0, %%cluster_ctarank;" : "=r"(rnk));
    const int r = (int)rnk;

    const float* lg = logit + (size_t)b * T_LEN;
    float* Lg   = g_L + (size_t)b * T_LEN * NI;
    float* outb = out + (size_t)b * T_LEN;

    // per-rank partition constants
    const int JB  = r ? SPLITJ : 0;
    const int NJ  = r ? (NI - SPLITJ) : SPLITJ;     // 38 / 44
    const int QN  = r ? 10 : 11;                    // j-quads (CTA1 pads j=82,83)
    const int NSP = r ? 7 : 6;                      // i-slices
    const int ISP = r ? 12 : 14;                    // i per slice
    const int BTH = QN * 14 * NSP;                  // 980 / 924
    const int NA  = NJ * CHUNK;                     // 1064 / 1232
    const int ATH = NA / 2;                         // 532 / 616
    const int PW  = 4 * QN;                         // 40 / 44
    const int QSZ = CHUNK * PW;
    const int NM  = r ? NM1 : NM0;
    const int NC  = (NM + 7) / 8;                   // 297 / 119

    // DSMEM peer bases
    const uint32_t peerL = mapa_rank(smem_u32(Lbuf), rnk ^ 1u);
    const uint32_t peerD = mapa_rank(smem_u32(dbuf), rnk ^ 1u);

    // ================= setup =================
    if (tid < NI) {               // trans row i = tid (fp64, matches numpy)
        double ti = (double)(28 + tid);
        double sum = 0.0;
        for (int jj = 0; jj < NI; ++jj)
            sum += exp(-100.0 * fabs((double)(28 + jj) / ti - 1.0));
        double ls = log(sum);
        for (int jj = 0; jj < NI; ++jj) {
            double rr = -100.0 * fabs((double)(28 + jj) / ti - 1.0);
            trans_t[tid * TROW + jj] = (float)(rr - ls);
        }
        trans_t[tid * TROW + 82] = -1e30f;
        trans_t[tid * TROW + 83] = -1e30f;
    }
    for (int s = tid; s < S_PAD; s += TPB) isf[s] = 0;
    for (int t = tid; t < T_LEN; t += TPB) {
        float x  = lg[t];
        float l1 = log1pf(expf(-fabsf(x)));
        blp[t] = fminf(x, 0.0f) - l1;
        nlp[t] = fminf(-x, 0.0f) - l1;
    }
    // cidx: own main-state ids (p >= 28)
    for (int k = tid; k < 8 * NC; k += TPB) {
        if (k < NM) {
            int kk = k + (r ? NM0 : 0);
            int j = (int)((1.0 + sqrt(8.0 * (double)kk + 1.0)) * 0.5);
            while ((j * (j + 1)) / 2 <= kk) ++j;
            while ((j * (j - 1)) / 2 > kk)  --j;
            int m = kk - (j * (j - 1)) / 2;
            cidx[k] = first_of(j) + 28 + m;
        } else cidx[k] = S_PAD - 1;
    }
    __syncthreads();
    if (tid < NI) isf[first_of(tid)] = 1;
    __syncthreads();

    const float logS = logf((float)S_TOT);
    for (int s = tid; s < S_TOT; s += TPB)
        dbuf[s] = (isf[s] ? blp[0] : nlp[0]) - logS;

    // ---- per-thread chunk-invariant constants ----
    // A tasks (2/thread, tid < ATH): task = g*NJ + q, j = JB + q
    int Ag[2], Aoff[2], Alb[2], Agn[2];
#pragma unroll
    for (int m = 0; m < 2; ++m) {
        int task = 2 * tid + m;
        if (task < NA) {
            int g = task / NJ, q = task - g * NJ, j = JB + q;
            Ag[m] = g; Aoff[m] = last_of(j) - g;
            Alb[m] = g * LR + j; Agn[m] = g * NI + j;
        } else { Ag[m] = 0; Aoff[m] = 0; Alb[m] = 0; Agn[m] = 0; }
    }
    // C-top tasks (2/thread, tid < ATH): task = p*NJ + q
    int Cth[2], Cpb[2], Cdn[2], Cbf[2];
#pragma unroll
    for (int m = 0; m < 2; ++m) {
        int task = 2 * tid + m;
        if (task < NA) {
            int p = task / NJ, q = task - p * NJ, j = JB + q;
            Cth[m] = 28 - p; Cpb[m] = (27 - p) * PW + q;
            Cdn[m] = first_of(j) + p; Cbf[m] = 27 - p;
        } else { Cth[m] = 28; Cpb[m] = 0; Cdn[m] = 0; Cbf[m] = 0; }
    }
    // B mapping (tid < BTH): i-slice h, local j-quad jq, frame pair f0
    const int h    = tid / (QN * 14);
    const int brem = tid - h * (QN * 14);
    const int jq   = brem / 14;
    const int f0   = 2 * (brem - 14 * jq);
    const int Bi0  = h * ISP;
    const int Bi1  = (Bi0 + ISP < NI) ? (Bi0 + ISP) : NI;
    __syncthreads();

    // ================= 214 full chunks =================
    for (int c = 0; c < NFULL; ++c) {
        const int t0 = 1 + CHUNK * c;
        const float* dprev = dbuf + (c & 1) * S_PAD;
        float*       dnew  = dbuf + ((c + 1) & 1) * S_PAD;
        const float* np    = nlp + t0;
        const int    lsel  = (c & 1) * LBSZ;
        float*       Lw    = Lbuf + lsel;
        const uint32_t LwP = peerL + (uint32_t)lsel * 4u;
        float* Lgc = Lg + (size_t)t0 * NI;

        // ---- A: own L chains (2-way ILP), write local + peer + global ----
        if (tid < ATH) {
            float a0 = dprev[Aoff[0]];
            float a1 = dprev[Aoff[1]];
            int kmax = Ag[0] > Ag[1] ? Ag[0] : Ag[1];
#pragma unroll 4
            for (int k = 0; k < kmax; ++k) {
                float v = np[k];
                if (k < Ag[0]) a0 += v;
                if (k < Ag[1]) a1 += v;
            }
            Lw[Alb[0]] = a0; st_cluster(LwP + 4u * Alb[0], a0); Lgc[Agn[0]] = a0;
            Lw[Alb[1]] = a1; st_cluster(LwP + 4u * Alb[1], a1); Lgc[Agn[1]] = a1;
        }
        CL_ARRIVE();

        // ---- C-main in the arrive->wait gap (purely CTA-local) ----
        if (tid >= ATH && tid < ATH + NC) {
            const int base = 8 * (tid - ATH);
            int s0 = cidx[base],     s1 = cidx[base + 1];
            int s2 = cidx[base + 2], s3 = cidx[base + 3];
            int s4 = cidx[base + 4], s5 = cidx[base + 5];
            int s6 = cidx[base + 6], s7 = cidx[base + 7];
            float m0 = dprev[s0 - CHUNK], m1 = dprev[s1 - CHUNK];
            float m2 = dprev[s2 - CHUNK], m3 = dprev[s3 - CHUNK];
            float m4 = dprev[s4 - CHUNK], m5 = dprev[s5 - CHUNK];
            float m6 = dprev[s6 - CHUNK], m7 = dprev[s7 - CHUNK];
#pragma unroll
            for (int k = 0; k < CHUNK; ++k) {
                float v = np[k];
                m0 += v; m1 += v; m2 += v; m3 += v;
                m4 += v; m5 += v; m6 += v; m7 += v;
            }
            if (base     < NM) dnew[s0] = m0;
            if (base + 1 < NM) dnew[s1] = m1;
            if (base + 2 < NM) dnew[s2] = m2;
            if (base + 3 < NM) dnew[s3] = m3;
            if (base + 4 < NM) dnew[s4] = m4;
            if (base + 5 < NM) dnew[s5] = m5;
            if (base + 6 < NM) dnew[s6] = m6;
            if (base + 7 < NM) dnew[s7] = m7;
        }
        CL_WAIT();   // both CTAs' L complete everywhere

        // ---- B: own j, i-slice, ~all threads ----
        if (tid < BTH) {
            const float4* tc = (const float4*)trans_t + ((JB >> 2) + jq);
            const float*  L0 = Lbuf + lsel + f0 * LR;
            const float*  L1 = L0 + LR;
            float4 A0 = make_float4(-1e30f, -1e30f, -1e30f, -1e30f);
            float4 A1 = A0;
#pragma unroll 4
            for (int i = Bi0; i < Bi1; ++i) {
                float4 tv = tc[i * (TROW / 4)];
                float l0 = L0[i];
                float l1 = L1[i];
                A0.x = fmaxf(A0.x, l0 + tv.x); A0.y = fmaxf(A0.y, l0 + tv.y);
                A0.z = fmaxf(A0.z, l0 + tv.z); A0.w = fmaxf(A0.w, l0 + tv.w);
                A1.x = fmaxf(A1.x, l1 + tv.x); A1.y = fmaxf(A1.y, l1 + tv.y);
                A1.z = fmaxf(A1.z, l1 + tv.z); A1.w = fmaxf(A1.w, l1 + tv.w);
            }
            float* Ph = Pbuf + h * QSZ;
            *(float4*)(Ph + f0 * PW + 4 * jq)       = A0;
            *(float4*)(Ph + (f0 + 1) * PW + 4 * jq) = A1;
        }
        __syncthreads();

        // ---- C-top: combine NSP partials, + blp, chain (2-way ILP) ----
        if (tid < ATH) {
            float c0 = -1e30f, c1 = -1e30f;
            for (int hh = 0; hh < NSP; ++hh) {
                const float* Ph = Pbuf + hh * QSZ;
                c0 = fmaxf(c0, Ph[Cpb[0]]);
                c1 = fmaxf(c1, Ph[Cpb[1]]);
            }
            c0 += blp[t0 + Cbf[0]];
            c1 += blp[t0 + Cbf[1]];
            int kmin = Cth[0] < Cth[1] ? Cth[0] : Cth[1];
#pragma unroll 4
            for (int k = kmin; k < CHUNK; ++k) {
                float v = np[k];
                if (k >= Cth[0]) c0 += v;
                if (k >= Cth[1]) c1 += v;
            }
            dnew[Cdn[0]] = c0;
            dnew[Cdn[1]] = c1;
        }
        __syncthreads();
    }

    // ================= exchange final delta partitions =================
    int ping = NFULL & 1;   // buffer holding delta at t=5992
    {
        const int slo = r ? SPLITS : 0;
        const int shi = r ? S_TOT : SPLITS;
        const float* dp = dbuf + ping * S_PAD;
        const uint32_t pd = peerD + (uint32_t)(ping * S_PAD) * 4u;
        for (int s = slo + tid; s < shi; s += TPB)
            st_cluster(pd + 4u * s, dp[s]);
    }
    CL_ARRIVE(); CL_WAIT();

    // ================= tail t = 5993..5999 (redundant, both CTAs) =========
    for (int t = 1 + CHUNK * NFULL; t < T_LEN; ++t) {
        const float* dprev = dbuf + ping * S_PAD;
        float*       dnew  = dbuf + (ping ^ 1) * S_PAD;
        if (tid < NI) {
            float lv = dprev[last_of(tid)];
            Pbuf[tid] = lv;                   // scratch
            Lg[(size_t)t * NI + tid] = lv;
        }
        __syncthreads();
        if (tid < NI) {
            float m = -1e30f;
            for (int i = 0; i < NI; ++i)
                m = fmaxf(m, Pbuf[i] + trans_t[i * TROW + tid]);
            dnew[first_of(tid)] = m + blp[t];
        } else if (tid >= 128) {
            float nb = nlp[t];
            for (int s = tid - 128; s < S_TOT; s += TPB - 128)
                if (!isf[s]) dnew[s] = dprev[s - 1] + nb;
        }
        __syncthreads();
        ping ^= 1;
    }

    // ================= final argmax (first-max = smallest s) ==============
    const float* df = dbuf + ping * S_PAD;
    if (r == 0) for (int t = tid; t < T_LEN; t += TPB) outb[t] = 0.0f;

    float bv = -INFINITY; int bs = 0x7fffffff;
    for (int s = tid; s < S_TOT; s += TPB) {
        float v = df[s];
        if (v > bv) { bv = v; bs = s; }
    }
#pragma unroll
    for (int off = 16; off; off >>= 1) {
        float ov = __shfl_xor_sync(0xffffffffu, bv, off);
        int   oi = __shfl_xor_sync(0xffffffffu, bs, off);
        if (ov > bv || (ov == bv && oi < bs)) { bv = ov; bs = oi; }
    }
    if ((tid & 31) == 0) { redv[tid >> 5] = bv; redi[tid >> 5] = bs; }
    __syncthreads();

    // ================= backtrace (rank 0, warp 0) =========================
    if (r == 0 && tid < 32) {
        bv = redv[tid]; bs = redi[tid];
#pragma unroll
        for (int off = 16; off; off >>= 1) {
            float ov = __shfl_xor_sync(0xffffffffu, bv, off);
            int   oi = __shfl_xor_sync(0xffffffffu, bs, off);
            if (ov > bv || (ov == bv && oi < bs)) { bv = ov; bs = oi; }
        }
        int lo = 0, hi = 81;
        while (lo < hi) { int mid = (lo + hi + 1) >> 1; if (first_of(mid) <= bs) lo = mid; else hi = mid - 1; }
        int j   = lo;
        int pos = bs - first_of(j);
        int t   = T_LEN - 1;
        const int lane = tid;

        while (true) {
            int te = t - pos;
            if (te < 0) break;
            if (lane == 0) {
                float x  = lg[te];
                float sg = 1.0f / (1.0f + expf(-x));
                if (sg >= 0.05f) outb[te] = 1.0f;
            }
            if (te == 0) break;
            const float* Lr = Lg + (size_t)te * NI;
            float best = -INFINITY; int bi = 0x7fffffff;
            for (int i = lane; i < NI; i += 32) {
                float cc = Lr[i] + trans_t[i * TROW + j];
                if (cc > best) { best = cc; bi = i; }
            }
#pragma unroll
            for (int off = 16; off; off >>= 1) {
                float ov = __shfl_xor_sync(0xffffffffu, best, off);
                int   oi = __shfl_xor_sync(0xffffffffu, bi,   off);
                if (ov > best || (ov == best && oi < bi)) { best = ov; bi = oi; }
            }
            j   = bi;
            pos = 27 + j;
            t   = te - 1;
        }
    }
    CL_ARRIVE(); CL_WAIT();
}

extern "C" void kernel_launch(void* const* d_in, const int* in_sizes, int n_in,
                              void* d_out, int out_size)
{
    (void)in_sizes; (void)n_in; (void)out_size;
    const float* logit = (const float*)d_in[0];
    float* out = (float*)d_out;

    const size_t smem = (size_t)(TROW * TROW + 2 * S_PAD + 2 * LBSZ + PBMAX
                                 + 2 * T_LEN + 64 + CIDXN) * 4 + S_PAD;
    cudaFuncSetAttribute(dbn_kernel,
                         cudaFuncAttributeMaxDynamicSharedMemorySize, (int)smem);

    cudaLaunchConfig_t cfg = {};
    cfg.gridDim  = dim3(2 * BATCH, 1, 1);
    cfg.blockDim = dim3(TPB, 1, 1);
    cfg.dynamicSmemBytes = smem;
    cfg.stream = 0;
    cudaLaunchAttribute attrs[1];
    attrs[0].id = cudaLaunchAttributeClusterDimension;
    attrs[0].val.clusterDim.x = 2;
    attrs[0].val.clusterDim.y = 1;
    attrs[0].val.clusterDim.z = 1;
    cfg.attrs = attrs;
    cfg.numAttrs = 1;
    cudaLaunchKernelEx(&cfg, dbn_kernel, logit, out);
}

// round 15
// speedup vs baseline: 1.8414x; 1.2197x over previous
#include <cuda_runtime.h>
#include <math.h>
#include <stdint.h>
#include <stddef.h>

// DBN beat decoder, prefix-sum collapsed Viterbi.
// tau = 28..109 (82 tempi), S = 5617, B = 4, T = 6000.
// All emission chains replaced by cumulative-sum differences; delta array
// eliminated; F ring + lazy backtrace carry the full state.
#define NI     82
#define TROW   84        // trans_t row stride (i-major)
#define LR     85        // Lbuf row stride
#define RB     84        // F ring row stride
#define RINGD  256
#define S_TOT  5617
#define T_LEN  6000
#define BATCH  4
#define TPB    1024
#define CHUNK  28
#define NCH    215       // chunks cover t = 1..5999 (last has 7 frames)
#define NTOPS  2296      // 28*82 tasks
#define QSZ    (CHUNK * RB)   // 2352, one partial plane
#define BTH    882       // B threads: 3 i-slices x 21 j-quads x 14 f-pairs

__device__ float g_L[(size_t)BATCH * T_LEN * NI];   // L values for lazy backtrace

__device__ __forceinline__ int first_of(int j) { return 28 * j + (j * (j - 1)) / 2; }

__global__ __launch_bounds__(TPB, 1)
void dbn_kernel(const float* __restrict__ logit, float* __restrict__ out)
{
    extern __shared__ char smraw[];
    float* trans_t = (float*)smraw;                 // [84][84] trans_t[i][j]
    float* Fring   = trans_t + TROW * TROW;         // [256][84]  F_t[j] at (t&255)
    float* Lbuf    = Fring + RINGD * RB;            // [28][85]
    float* Pbuf    = Lbuf + CHUNK * LR;             // [3][28][84] B partials (+scan scratch)
    float* cum     = Pbuf + 3 * QSZ;                // 6000: cum[t] = nlp[0..t]
    float* blp     = cum + T_LEN;                   // 6000
    float* redv    = blp + T_LEN;                   // 32
    int*   redi    = (int*)(redv + 32);             // 32

    const int tid = threadIdx.x;
    const int b   = blockIdx.x;
    const float* lg = logit + (size_t)b * T_LEN;
    float* Lg   = g_L + (size_t)b * T_LEN * NI;
    float* outb = out + (size_t)b * T_LEN;

    // ================= setup =================
    if (tid < NI) {               // trans row i = tid (fp64, matches numpy)
        double ti = (double)(28 + tid);
        double sum = 0.0;
        for (int jj = 0; jj < NI; ++jj)
            sum += exp(-100.0 * fabs((double)(28 + jj) / ti - 1.0));
        double ls = log(sum);
        for (int jj = 0; jj < NI; ++jj) {
            double rr = -100.0 * fabs((double)(28 + jj) / ti - 1.0);
            trans_t[tid * TROW + jj] = (float)(rr - ls);
        }
        trans_t[tid * TROW + 82] = -1e30f;
        trans_t[tid * TROW + 83] = -1e30f;
    }
    for (int t = tid; t < T_LEN; t += TPB) {
        float x  = lg[t];
        float l1 = log1pf(expf(-fabsf(x)));
        blp[t] = fminf(x, 0.0f) - l1;
        cum[t] = fminf(-x, 0.0f) - l1;     // nlp, scanned in place below
    }
    __syncthreads();

    // ---- block-wide inclusive scan of cum[0..5999] (6 elems/thread) ----
    {
        float* part  = Pbuf;          // 1000 scratch
        float* gpart = Pbuf + 1024;   // 32 scratch
        if (tid < 1000) {
            int base = 6 * tid;
            float a = cum[base];
            cum[base] = a;
            for (int k = 1; k < 6; ++k) { a += cum[base + k]; cum[base + k] = a; }
            part[tid] = a;
        }
        __syncthreads();
        if (tid < 32) {
            float acc = 0.0f;
            for (int k = 0; k < 32; ++k) {
                int idx = 32 * tid + k;
                if (idx < 1000) { float v = part[idx]; part[idx] = acc; acc += v; }
            }
            float x = acc;
#pragma unroll
            for (int off = 1; off < 32; off <<= 1) {
                float y = __shfl_up_sync(0xffffffffu, x, off);
                if ((tid & 31) >= off) x += y;
            }
            gpart[tid] = x - acc;    // exclusive group offset
        }
        __syncthreads();
        if (tid < 1000) {
            float off = part[tid] + gpart[tid >> 5];
            int base = 6 * tid;
#pragma unroll
            for (int k = 0; k < 6; ++k) cum[base + k] += off;
        }
    }
    __syncthreads();

    const float logS = logf((float)S_TOT);
    if (tid < NI) Fring[0 * RB + tid] = blp[0] - logS;   // F_0[j]

    // ---- per-thread chunk-invariant constants ----
    // A tasks (3/thread): task = g*82 + j. st = t0 + g - tau_j = t0 + D
    int Ag[3], Aj[3], AD[3], Alb[3];
#pragma unroll
    for (int m = 0; m < 3; ++m) {
        int task = 3 * tid + m;
        if (task < NTOPS) {
            int g = task / NI, j = task - g * NI;
            Ag[m] = g; Aj[m] = j; AD[m] = g - 28 - j; Alb[m] = g * LR + j;
        } else { Ag[m] = 28; Aj[m] = 0; AD[m] = -200; Alb[m] = 0; }
    }
    // combine tasks (3/thread): task = f*82 + j
    int Kf[3], Kj[3], Kpb[3];
#pragma unroll
    for (int m = 0; m < 3; ++m) {
        int task = 3 * tid + m;
        if (task < NTOPS) {
            int f = task / NI, j = task - f * NI;
            Kf[m] = f; Kj[m] = j; Kpb[m] = f * RB + j;
        } else { Kf[m] = 28; Kj[m] = 0; Kpb[m] = 0; }
    }
    // B mapping (tid < BTH): i-slice h, j-quad jq, frame pair f0
    const int h    = tid / 294;
    const int brem = tid - h * 294;
    const int jq   = brem / 14;
    const int f0   = 2 * (brem - 14 * jq);
    const int Bi0  = (h == 0) ? 0 : (h == 1) ? 28 : 55;
    const int Bi1  = (h == 0) ? 28 : (h == 1) ? 55 : 82;
    __syncthreads();

    // ================= 215 chunks, 3 barriers each =================
    for (int c = 0; c < NCH; ++c) {
        const int t0 = 1 + CHUNK * c;
        int NF = T_LEN - t0; if (NF > CHUNK) NF = CHUNK;
        float* Lgc = Lg + (size_t)t0 * NI;

        // ---- A: L[g][j] = F_{st}[j] + (cum[t-1]-cum[st]),  one add per task ----
#pragma unroll
        for (int m = 0; m < 3; ++m) {
            if (Ag[m] < NF) {
                int g  = Ag[m], j = Aj[m];
                int st = t0 + AD[m];
                float ce = cum[t0 + g - 1];
                float v;
                if (st >= 0) v = Fring[(st & (RINGD - 1)) * RB + j] + (ce - cum[st]);
                else         v = ce - logS;
                Lbuf[Alb[m]] = v;
                Lgc[g * NI + j] = v;
            }
        }
        __syncthreads();

        // ---- B: partial max over i-slice for (4j x 2f) tile ----
        if (tid < BTH) {
            const float4* tc = (const float4*)trans_t + jq;
            const float*  L0 = Lbuf + f0 * LR;
            const float*  L1 = L0 + LR;
            float4 A0 = make_float4(-1e30f, -1e30f, -1e30f, -1e30f);
            float4 A1 = A0;
#pragma unroll 4
            for (int i = Bi0; i < Bi1; ++i) {
                float4 tv = tc[i * (TROW / 4)];
                float l0 = L0[i];
                float l1 = L1[i];
                A0.x = fmaxf(A0.x, l0 + tv.x); A0.y = fmaxf(A0.y, l0 + tv.y);
                A0.z = fmaxf(A0.z, l0 + tv.z); A0.w = fmaxf(A0.w, l0 + tv.w);
                A1.x = fmaxf(A1.x, l1 + tv.x); A1.y = fmaxf(A1.y, l1 + tv.y);
                A1.z = fmaxf(A1.z, l1 + tv.z); A1.w = fmaxf(A1.w, l1 + tv.w);
            }
            float* Ph = Pbuf + h * QSZ;
            *(float4*)(Ph + f0 * RB + 4 * jq)       = A0;
            *(float4*)(Ph + (f0 + 1) * RB + 4 * jq) = A1;
        }
        __syncthreads();

        // ---- combine: F_t[j] = max3(partials) + blp[t] -> Fring ----
#pragma unroll
        for (int m = 0; m < 3; ++m) {
            if (Kf[m] < NF) {
                int f = Kf[m], j = Kj[m];
                float v = fmaxf(fmaxf(Pbuf[Kpb[m]], Pbuf[QSZ + Kpb[m]]),
                                Pbuf[2 * QSZ + Kpb[m]]) + blp[t0 + f];
                Fring[((t0 + f) & (RINGD - 1)) * RB + j] = v;
            }
        }
        __syncthreads();
    }

    // ================= final argmax over delta_{T-1} (first-max) ==========
    for (int t = tid; t < T_LEN; t += TPB) outb[t] = 0.0f;

    const float cend = cum[T_LEN - 1];
    float bv = -INFINITY; int bs = 0x7fffffff;
    for (int s = tid; s < S_TOT; s += TPB) {
        int lo = 0, hi = 81;
        while (lo < hi) { int mid = (lo + hi + 1) >> 1; if (first_of(mid) <= s) lo = mid; else hi = mid - 1; }
        int j = lo;
        int p = s - first_of(j);
        int tf = T_LEN - 1 - p;
        float v = Fring[(tf & (RINGD - 1)) * RB + j] + (cend - cum[tf]);
        if (v > bv) { bv = v; bs = s; }
    }
#pragma unroll
    for (int off = 16; off; off >>= 1) {
        float ov = __shfl_xor_sync(0xffffffffu, bv, off);
        int   oi = __shfl_xor_sync(0xffffffffu, bs, off);
        if (ov > bv || (ov == bv && oi < bs)) { bv = ov; bs = oi; }
    }
    if ((tid & 31) == 0) { redv[tid >> 5] = bv; redi[tid >> 5] = bs; }
    __syncthreads();

    // ================= warp-cooperative lazy backtrace =====================
    if (tid < 32) {
        bv = redv[tid]; bs = redi[tid];
#pragma unroll
        for (int off = 16; off; off >>= 1) {
            float ov = __shfl_xor_sync(0xffffffffu, bv, off);
            int   oi = __shfl_xor_sync(0xffffffffu, bs, off);
            if (ov > bv || (ov == bv && oi < bs)) { bv = ov; bs = oi; }
        }
        int lo = 0, hi = 81;
        while (lo < hi) { int mid = (lo + hi + 1) >> 1; if (first_of(mid) <= bs) lo = mid; else hi = mid - 1; }
        int j   = lo;
        int pos = bs - first_of(j);
        int t   = T_LEN - 1;
        const int lane = tid;

        while (true) {
            int te = t - pos;
            if (te < 0) break;
            if (lane == 0) {
                float x  = lg[te];
                float sg = 1.0f / (1.0f + expf(-x));
                if (sg >= 0.05f) outb[te] = 1.0f;
            }
            if (te == 0) break;
            const float* Lr = Lg + (size_t)te * NI;
            float best = -INFINITY; int bi = 0x7fffffff;
            for (int i = lane; i < NI; i += 32) {
                float cc = Lr[i] + trans_t[i * TROW + j];
                if (cc > best) { best = cc; bi = i; }
            }
#pragma unroll
            for (int off = 16; off; off >>= 1) {
                float ov = __shfl_xor_sync(0xffffffffu, best, off);
                int   oi = __shfl_xor_sync(0xffffffffu, bi,   off);
                if (ov > best || (ov == best && oi < bi)) { best = ov; bi = oi; }
            }
            j   = bi;
            pos = 27 + j;
            t   = te - 1;
        }
    }
}

extern "C" void kernel_launch(void* const* d_in, const int* in_sizes, int n_in,
                              void* d_out, int out_size)
{
    (void)in_sizes; (void)n_in; (void)out_size;
    const float* logit = (const float*)d_in[0];
    float* out = (float*)d_out;

    const size_t smem = (size_t)(TROW * TROW + RINGD * RB + CHUNK * LR
                                 + 3 * QSZ + 2 * T_LEN + 64) * 4;
    cudaFuncSetAttribute(dbn_kernel,
                         cudaFuncAttributeMaxDynamicSharedMemorySize, (int)smem);
    dbn_kernel<<<BATCH, TPB, smem>>>(logit, out);
}